// round 8
// baseline (speedup 1.0000x reference)
#include <cuda_runtime.h>
#include <cuda_bf16.h>
#include <cstdint>
#include <cstddef>

// ---------------- problem constants ----------------
#define NODES 2048
#define EDGES 65536
#define PAIRS 1000000
#define LAYERS 4
#define HEADS 8
#define DIM 256
#define DINV 128
#define DOUTV 64
#define MAXDEGV 64
#define MPDV 10
#define SCALEQ 0.0625f

// ---------------- device scratch (no allocation allowed) ----------------
__device__ __align__(16) float g_h [NODES*DIM];
__device__ __align__(16) float g_hn[NODES*DIM];
__device__ __align__(16) float g_xp[NODES*DIM];
__device__ __align__(16) float g_q [HEADS*NODES*DIM];
__device__ __align__(16) float g_k [HEADS*NODES*DIM];
__device__ __align__(16) float g_v [HEADS*NODES*DIM];
__device__ __align__(16) float g_o [NODES*HEADS*DIM];
__device__ __align__(16) float g_S [(size_t)HEADS*NODES*NODES];
__device__ __align__(16) float g_bmat[(size_t)NODES*NODES];
__device__ int   g_deg[NODES];
__device__ float g_rmax[HEADS*NODES];
__device__ float g_rinv[HEADS*NODES];

// bf16 split operands
__device__ __align__(16) __nv_bfloat16 g_khi [HEADS*NODES*DIM];
__device__ __align__(16) __nv_bfloat16 g_klo [HEADS*NODES*DIM];
__device__ __align__(16) __nv_bfloat16 g_vthi[HEADS*NODES*DIM];
__device__ __align__(16) __nv_bfloat16 g_vtlo[HEADS*NODES*DIM];
__device__ __align__(16) __nv_bfloat16 g_wqhi[LAYERS*HEADS*DIM*DIM];
__device__ __align__(16) __nv_bfloat16 g_wqlo[LAYERS*HEADS*DIM*DIM];
__device__ __align__(16) __nv_bfloat16 g_wkhi[LAYERS*HEADS*DIM*DIM];
__device__ __align__(16) __nv_bfloat16 g_wklo[LAYERS*HEADS*DIM*DIM];
__device__ __align__(16) __nv_bfloat16 g_wvhi[LAYERS*HEADS*DIM*DIM];
__device__ __align__(16) __nv_bfloat16 g_wvlo[LAYERS*HEADS*DIM*DIM];
__device__ __align__(16) __nv_bfloat16 g_wohi[LAYERS*HEADS*DIM*DIM];
__device__ __align__(16) __nv_bfloat16 g_wolo[LAYERS*HEADS*DIM*DIM];
__device__ __align__(16) __nv_bfloat16 g_wffhi[LAYERS*DIM*DIM];
__device__ __align__(16) __nv_bfloat16 g_wfflo[LAYERS*DIM*DIM];

// ---------------- helpers ----------------
__device__ __forceinline__ uint32_t smem_to_u32(const void* p) {
    uint32_t a;
    asm("{ .reg .u64 t; cvta.to.shared.u64 t, %1; cvt.u32.u64 %0, t; }" : "=r"(a) : "l"(p));
    return a;
}
__device__ __forceinline__ uint32_t pack_bf2(__nv_bfloat16 a, __nv_bfloat16 b) {
    return (uint32_t)__bfloat16_as_ushort(a) | ((uint32_t)__bfloat16_as_ushort(b) << 16);
}
__device__ __forceinline__ void ldsm4(uint32_t* r, uint32_t addr) {
    asm volatile("ldmatrix.sync.aligned.m8n8.x4.shared.b16 {%0,%1,%2,%3}, [%4];"
        : "=r"(r[0]), "=r"(r[1]), "=r"(r[2]), "=r"(r[3]) : "r"(addr));
}
__device__ __forceinline__ void ldsm2(uint32_t* r, uint32_t addr) {
    asm volatile("ldmatrix.sync.aligned.m8n8.x2.shared.b16 {%0,%1}, [%2];"
        : "=r"(r[0]), "=r"(r[1]) : "r"(addr));
}
__device__ __forceinline__ void mma_bf16(float* d, const uint32_t* a, const uint32_t* b) {
    asm volatile("mma.sync.aligned.m16n8k16.row.col.f32.bf16.bf16.f32 "
        "{%0,%1,%2,%3}, {%4,%5,%6,%7}, {%8,%9}, {%0,%1,%2,%3};"
        : "+f"(d[0]), "+f"(d[1]), "+f"(d[2]), "+f"(d[3])
        : "r"(a[0]), "r"(a[1]), "r"(a[2]), "r"(a[3]), "r"(b[0]), "r"(b[1]));
}

// ---------------- utility kernels ----------------
__global__ void zero_deg_kernel() {
    int i = blockIdx.x * blockDim.x + threadIdx.x;
    if (i < NODES) g_deg[i] = 0;
}
__global__ void zero_bmat_kernel() {
    size_t i = (size_t)blockIdx.x * blockDim.x + threadIdx.x;
    size_t stride = (size_t)gridDim.x * blockDim.x;
    for (; i < (size_t)NODES*NODES; i += stride) g_bmat[i] = 0.f;
}
__global__ void deg_kernel(const int* __restrict__ edge_index) {
    int e = blockIdx.x * blockDim.x + threadIdx.x;
    if (e < EDGES) atomicAdd(&g_deg[edge_index[e]], 1);
}
__global__ void scatter_kernel(const int* __restrict__ dindex,
                               const int* __restrict__ dist,
                               const float* __restrict__ bsp) {
    int p = blockIdx.x * blockDim.x + threadIdx.x;
    if (p >= PAIRS) return;
    int i = dindex[p];
    int j = dindex[PAIRS + p];
    int d = dist[p];
    d = d < 0 ? 0 : (d > MPDV-1 ? MPDV-1 : d);
    g_bmat[(size_t)i*NODES + j] = bsp[d];
}

__global__ void input_kernel(const float* __restrict__ x,
                             const float* __restrict__ Win,
                             const float* __restrict__ b_in,
                             const float* __restrict__ z) {
    int row = blockIdx.x;
    int c   = threadIdx.x;
    __shared__ float xs[DINV];
    if (c < DINV) xs[c] = x[row*DINV + c];
    __syncthreads();
    float acc = 0.f;
    #pragma unroll 8
    for (int k = 0; k < DINV; k++) acc += xs[k] * Win[k*DIM + c];
    int d = g_deg[row];
    if (d > MAXDEGV-1) d = MAXDEGV-1;
    g_h[row*DIM + c] = acc + b_in[c] + z[d*DIM + c];
}

__global__ void ln_kernel(const float* __restrict__ x, float* __restrict__ y,
                          const float* __restrict__ w, const float* __restrict__ b) {
    int row = blockIdx.x;
    int t = threadIdx.x;
    __shared__ float red[256];
    float v = x[row*DIM + t];
    red[t] = v; __syncthreads();
    #pragma unroll
    for (int s = 128; s > 0; s >>= 1) { if (t < s) red[t] += red[t+s]; __syncthreads(); }
    float mu = red[0] * (1.f/DIM);
    __syncthreads();
    float d = v - mu;
    red[t] = d*d; __syncthreads();
    #pragma unroll
    for (int s = 128; s > 0; s >>= 1) { if (t < s) red[t] += red[t+s]; __syncthreads(); }
    float var = red[0] * (1.f/DIM);
    y[row*DIM + t] = d * rsqrtf(var + 1e-5f) * w[t] + b[t];
}

// row stats over masked scores s' (already scaled + biased + mneg-multiplied).
// dead row (all same-graph exps underflow): rinv = 0.
__global__ void __launch_bounds__(256) rowstat_kernel(const int* __restrict__ gptr) {
    int row = blockIdx.x, h = blockIdx.y;
    const float* srow = g_S + ((size_t)h*NODES + row)*NODES;
    __shared__ float sv[NODES];
    __shared__ int   sp[NODES];
    __shared__ float red[256];
    int t = threadIdx.x;
    for (int j = t; j < NODES; j += 256) { sv[j] = srow[j]; sp[j] = gptr[j]; }
    __syncthreads();
    int pn = sp[row];
    float mall = -3.4e38f, msame = -3.4e38f;
    for (int j = t; j < NODES; j += 256) {
        float xv = sv[j];
        mall = fmaxf(mall, xv);
        if (sp[j] == pn) msame = fmaxf(msame, xv);
    }
    red[t] = mall; __syncthreads();
    #pragma unroll
    for (int s = 128; s > 0; s >>= 1) { if (t < s) red[t] = fmaxf(red[t], red[t+s]); __syncthreads(); }
    mall = red[0]; __syncthreads();
    red[t] = msame; __syncthreads();
    #pragma unroll
    for (int s = 128; s > 0; s >>= 1) { if (t < s) red[t] = fmaxf(red[t], red[t+s]); __syncthreads(); }
    msame = red[0]; __syncthreads();

    float rmax, rinv;
    if (mall - msame > 80.f) {
        rmax = 3.4e38f; rinv = 0.f;      // dead row: attention output exactly ~0
    } else {
        float s = 0.f;                    // rare path: exact reference denominator
        for (int j = t; j < NODES; j += 256) s += __expf(sv[j] - mall);
        red[t] = s; __syncthreads();
        #pragma unroll
        for (int q = 128; q > 0; q >>= 1) { if (t < q) red[t] += red[t+q]; __syncthreads(); }
        rmax = mall; rinv = 1.f / red[0];
    }
    if (t == 0) { g_rmax[h*NODES + row] = rmax; g_rinv[h*NODES + row] = rinv; }
}

// elementwise fp32 -> bf16 hi/lo split (same layout)
__global__ void split_kernel(const float* __restrict__ in,
                             __nv_bfloat16* __restrict__ hi,
                             __nv_bfloat16* __restrict__ lo, int n4) {
    int i = blockIdx.x * blockDim.x + threadIdx.x;
    if (i >= n4) return;
    float4 v = ((const float4*)in)[i];
    __nv_bfloat16 h0 = __float2bfloat16(v.x);
    __nv_bfloat16 h1 = __float2bfloat16(v.y);
    __nv_bfloat16 h2 = __float2bfloat16(v.z);
    __nv_bfloat16 h3 = __float2bfloat16(v.w);
    __nv_bfloat16 l0 = __float2bfloat16(v.x - __bfloat162float(h0));
    __nv_bfloat16 l1 = __float2bfloat16(v.y - __bfloat162float(h1));
    __nv_bfloat16 l2 = __float2bfloat16(v.z - __bfloat162float(h2));
    __nv_bfloat16 l3 = __float2bfloat16(v.w - __bfloat162float(h3));
    ((uint2*)hi)[i] = make_uint2(pack_bf2(h0,h1), pack_bf2(h2,h3));
    ((uint2*)lo)[i] = make_uint2(pack_bf2(l0,l1), pack_bf2(l2,l3));
}

// transpose + split: in [batch][Krows][Ncols] fp32 -> out [batch][Ncols][Krows] bf16 hi/lo
__global__ void tsplit_kernel(const float* __restrict__ in, long long inB,
                              int Krows, int Ncols,
                              __nv_bfloat16* __restrict__ hi,
                              __nv_bfloat16* __restrict__ lo, long long outB) {
    __shared__ float t[32][33];
    const float* inb = in + (size_t)blockIdx.z * inB;
    int n0 = blockIdx.x * 32, k0 = blockIdx.y * 32;
    #pragma unroll
    for (int j = 0; j < 4; j++)
        t[threadIdx.y + j*8][threadIdx.x] =
            inb[(size_t)(k0 + threadIdx.y + j*8) * Ncols + n0 + threadIdx.x];
    __syncthreads();
    size_t ob = (size_t)blockIdx.z * outB;
    #pragma unroll
    for (int j = 0; j < 4; j++) {
        int n = threadIdx.y + j*8;
        float v = t[threadIdx.x][n];
        size_t o = ob + (size_t)(n0 + n) * Krows + k0 + threadIdx.x;
        __nv_bfloat16 hv = __float2bfloat16(v);
        hi[o] = hv;
        lo[o] = __float2bfloat16(v - __bfloat162float(hv));
    }
}

// ---------------- split-bf16 GEMM via mma.sync ----------
// AMODE 0: A fp32 plain.  AMODE 1: A = masked scores s'; loader computes
//          p = exp(s'-rmax)*rinv for same-graph cols, 0 otherwise; per-CTA
//          early-out (zero tile) when all 128 rows dead.
// EPI 0: optional bias[n] + residual add.  EPI 1: attention score epilogue:
//          s' = (acc*SCALEQ + bmat[m][n]) * (ptr[m]==ptr[n] ? 1 : -1e6).
#define KC 64
#define PADE 72
#define SA_HI 0
#define SA_LO 18432
#define SB_HI 36864
#define SB_LO 55296
#define TCG_SMEM 73728

template<int AMODE, int EPI>
__global__ void __launch_bounds__(256, 1) tcgemm(
        const float* __restrict__ A, long long aB, int lda,
        const __nv_bfloat16* __restrict__ Bhi, const __nv_bfloat16* __restrict__ Blo,
        long long bB, int ldb,
        float* __restrict__ C, long long cB, int ldc, int K,
        const float* __restrict__ bias, long long biasB,
        const float* __restrict__ res, int ldres,
        const int* __restrict__ gptr, const float* __restrict__ rmax,
        const float* __restrict__ rinv, const float* __restrict__ bmatp) {
    extern __shared__ char smc[];
    uint32_t sbase = smem_to_u32(smc);

    int tid = threadIdx.x;
    int wid = tid >> 5, lane = tid & 31;
    int m0 = blockIdx.y * 128, n0 = blockIdx.x * 128;
    const float* Ab = A + (size_t)blockIdx.z * aB + (size_t)m0 * lda;
    const __nv_bfloat16* Bh = Bhi + (size_t)blockIdx.z * bB + (size_t)n0 * ldb;
    const __nv_bfloat16* Bl = Blo + (size_t)blockIdx.z * bB + (size_t)n0 * ldb;
    float* Cb = C + (size_t)blockIdx.z * cB;

    // loader indices
    int ra = tid >> 4, ca = (tid & 15) * 4;   // A: float4
    int rb = tid >> 3, cb = (tid & 7) * 8;    // B: uint4 (8 bf16)

    float prm[8], pri[8];
    int   ppm[8];
    if (AMODE == 1) {
        __shared__ int s_alive;
        if (tid == 0) s_alive = 0;
        __syncthreads();
        if (tid < 128 && rinv[(size_t)blockIdx.z*NODES + m0 + tid] != 0.f) s_alive = 1;
        __syncthreads();
        if (!s_alive) {       // all rows dead -> output tile is exactly zero
            float4 z4 = make_float4(0.f, 0.f, 0.f, 0.f);
            for (int idx = tid; idx < 128*32; idx += 256) {
                int r = idx >> 5, c4 = idx & 31;
                *(float4*)(Cb + (size_t)(m0 + r)*ldc + n0 + c4*4) = z4;
            }
            return;
        }
        #pragma unroll
        for (int p = 0; p < 8; p++) {
            int gr = m0 + p*16 + ra;
            prm[p] = rmax[(size_t)blockIdx.z*NODES + gr];
            pri[p] = rinv[(size_t)blockIdx.z*NODES + gr];
            ppm[p] = gptr[gr];
        }
    }

    // warp tile origin
    int wm = (wid & 1) * 64;
    int wn = (wid >> 1) * 32;

    uint32_t aAddr = sbase + ((uint32_t)((wm + (lane & 15)) * PADE + ((lane >> 4) << 3)) << 1);
    int l2 = lane & 15;
    uint32_t bAddr = sbase + ((uint32_t)((wn + (l2 & 7)) * PADE + (((l2 >> 3) & 1) << 3)) << 1);

    float acc[4][4][4];
    #pragma unroll
    for (int i = 0; i < 4; i++)
        #pragma unroll
        for (int j = 0; j < 4; j++)
            #pragma unroll
            for (int q = 0; q < 4; q++) acc[i][j][q] = 0.f;

    // prefetch chunk 0
    float4 pa[8];
    uint4 pbh[4], pbl[4];
    int4 pcv = make_int4(0,0,0,0);
    #pragma unroll
    for (int p = 0; p < 8; p++)
        pa[p] = *(const float4*)(Ab + (size_t)(p*16 + ra)*lda + ca);
    if (AMODE == 1) pcv = *(const int4*)(gptr + ca);
    #pragma unroll
    for (int p = 0; p < 4; p++) {
        pbh[p] = *(const uint4*)(Bh + (size_t)(p*32 + rb)*ldb + cb);
        pbl[p] = *(const uint4*)(Bl + (size_t)(p*32 + rb)*ldb + cb);
    }

    int nch = K / KC;
    for (int c = 0; c < nch; c++) {
        __syncthreads();
        #pragma unroll
        for (int p = 0; p < 8; p++) {
            float4 v = pa[p];
            if (AMODE == 1) {
                float4 q;
                if (pri[p] == 0.f) {
                    q = make_float4(0.f, 0.f, 0.f, 0.f);
                } else {
                    bool b0 = (pcv.x == ppm[p]), b1 = (pcv.y == ppm[p]);
                    bool b2 = (pcv.z == ppm[p]), b3 = (pcv.w == ppm[p]);
                    if (b0 | b1 | b2 | b3) {
                        float rm = prm[p], ri = pri[p];
                        q.x = b0 ? __expf(v.x - rm) * ri : 0.f;
                        q.y = b1 ? __expf(v.y - rm) * ri : 0.f;
                        q.z = b2 ? __expf(v.z - rm) * ri : 0.f;
                        q.w = b3 ? __expf(v.w - rm) * ri : 0.f;
                    } else {
                        q = make_float4(0.f, 0.f, 0.f, 0.f);
                    }
                }
                v = q;
            }
            __nv_bfloat16 h0 = __float2bfloat16(v.x);
            __nv_bfloat16 h1 = __float2bfloat16(v.y);
            __nv_bfloat16 h2 = __float2bfloat16(v.z);
            __nv_bfloat16 h3 = __float2bfloat16(v.w);
            __nv_bfloat16 l0 = __float2bfloat16(v.x - __bfloat162float(h0));
            __nv_bfloat16 l1 = __float2bfloat16(v.y - __bfloat162float(h1));
            __nv_bfloat16 l2b = __float2bfloat16(v.z - __bfloat162float(h2));
            __nv_bfloat16 l3 = __float2bfloat16(v.w - __bfloat162float(h3));
            uint32_t off = (uint32_t)(((p*16 + ra)*PADE + ca) << 1);
            *(uint2*)(smc + SA_HI + off) = make_uint2(pack_bf2(h0,h1), pack_bf2(h2,h3));
            *(uint2*)(smc + SA_LO + off) = make_uint2(pack_bf2(l0,l1), pack_bf2(l2b,l3));
        }
        #pragma unroll
        for (int p = 0; p < 4; p++) {
            uint32_t off = (uint32_t)(((p*32 + rb)*PADE + cb) << 1);
            *(uint4*)(smc + SB_HI + off) = pbh[p];
            *(uint4*)(smc + SB_LO + off) = pbl[p];
        }
        if (c + 1 < nch) {
            int k0 = (c + 1) * KC;
            #pragma unroll
            for (int p = 0; p < 8; p++)
                pa[p] = *(const float4*)(Ab + (size_t)(p*16 + ra)*lda + k0 + ca);
            if (AMODE == 1) pcv = *(const int4*)(gptr + k0 + ca);
            #pragma unroll
            for (int p = 0; p < 4; p++) {
                pbh[p] = *(const uint4*)(Bh + (size_t)(p*32 + rb)*ldb + k0 + cb);
                pbl[p] = *(const uint4*)(Bl + (size_t)(p*32 + rb)*ldb + k0 + cb);
            }
        }
        __syncthreads();
        #pragma unroll
        for (int kk = 0; kk < 4; kk++) {
            uint32_t ah[4][4], al[4][4], bh2[4][2], bl2[4][2];
            #pragma unroll
            for (int i = 0; i < 4; i++) {
                uint32_t ao = (uint32_t)(i*16*PADE*2 + kk*32);
                ldsm4(ah[i], aAddr + SA_HI + ao);
                ldsm4(al[i], aAddr + SA_LO + ao);
            }
            #pragma unroll
            for (int j = 0; j < 4; j++) {
                uint32_t bo = (uint32_t)(j*8*PADE*2 + kk*32);
                ldsm2(bh2[j], bAddr + SB_HI + bo);
                ldsm2(bl2[j], bAddr + SB_LO + bo);
            }
            #pragma unroll
            for (int i = 0; i < 4; i++)
                #pragma unroll
                for (int j = 0; j < 4; j++) {
                    mma_bf16(acc[i][j], ah[i], bh2[j]);
                    mma_bf16(acc[i][j], ah[i], bl2[j]);
                    mma_bf16(acc[i][j], al[i], bh2[j]);
                }
        }
    }

    int g = lane >> 2, t = lane & 3;
    if (EPI == 1) {
        // attention score epilogue: s' = (acc*scale + bmat) * mneg
        #pragma unroll
        for (int i = 0; i < 4; i++) {
            int m = m0 + wm + i*16 + g;
            int pma = gptr[m], pmb = gptr[m+8];
            const float* bra = bmatp + (size_t)m*NODES;
            const float* brb = bmatp + (size_t)(m+8)*NODES;
            #pragma unroll
            for (int j = 0; j < 4; j++) {
                int n = n0 + wn + j*8 + t*2;
                int pn0 = gptr[n], pn1 = gptr[n+1];
                float2 b0 = *(const float2*)(bra + n);
                float2 b1 = *(const float2*)(brb + n);
                float s00 = acc[i][j][0]*SCALEQ + b0.x;
                float s01 = acc[i][j][1]*SCALEQ + b0.y;
                float s10 = acc[i][j][2]*SCALEQ + b1.x;
                float s11 = acc[i][j][3]*SCALEQ + b1.y;
                s00 = (pma == pn0) ? s00 : s00 * -1e6f;
                s01 = (pma == pn1) ? s01 : s01 * -1e6f;
                s10 = (pmb == pn0) ? s10 : s10 * -1e6f;
                s11 = (pmb == pn1) ? s11 : s11 * -1e6f;
                *(float2*)(Cb + (size_t)m*ldc + n)     = make_float2(s00, s01);
                *(float2*)(Cb + (size_t)(m+8)*ldc + n) = make_float2(s10, s11);
            }
        }
    } else {
        const float* biasb = bias ? bias + (size_t)blockIdx.z * biasB : nullptr;
        #pragma unroll
        for (int i = 0; i < 4; i++) {
            int m = m0 + wm + i*16 + g;
            #pragma unroll
            for (int j = 0; j < 4; j++) {
                int n = n0 + wn + j*8 + t*2;
                float2 v0 = make_float2(acc[i][j][0], acc[i][j][1]);
                float2 v1 = make_float2(acc[i][j][2], acc[i][j][3]);
                if (biasb) {
                    float b0 = biasb[n], b1 = biasb[n+1];
                    v0.x += b0; v0.y += b1;
                    v1.x += b0; v1.y += b1;
                }
                if (res) {
                    float2 r0 = *(const float2*)(res + (size_t)m*ldres + n);
                    float2 r1 = *(const float2*)(res + (size_t)(m+8)*ldres + n);
                    v0.x += r0.x; v0.y += r0.y;
                    v1.x += r1.x; v1.y += r1.y;
                }
                *(float2*)(Cb + (size_t)m*ldc + n)     = v0;
                *(float2*)(Cb + (size_t)(m+8)*ldc + n) = v1;
            }
        }
    }
}

// out = h @ Wout + b_out
__global__ void out_kernel(const float* __restrict__ Wout,
                           const float* __restrict__ bout,
                           float* __restrict__ out) {
    int row = blockIdx.x;
    int c = threadIdx.x;
    __shared__ float hs[DIM];
    for (int k = c; k < DIM; k += DOUTV) hs[k] = g_h[row*DIM + k];
    __syncthreads();
    float acc = 0.f;
    #pragma unroll 8
    for (int k = 0; k < DIM; k++) acc += hs[k] * Wout[k*DOUTV + c];
    out[row*DOUTV + c] = acc + bout[c];
}

// ---------------- launch ----------------
extern "C" void kernel_launch(void* const* d_in, const int* in_sizes, int n_in,
                              void* d_out, int out_size) {
    (void)in_sizes; (void)n_in; (void)out_size;
    const float* x             = (const float*)d_in[0];
    const int*   edge_index    = (const int*)  d_in[1];
    const int*   ptr           = (const int*)  d_in[2];
    const int*   distances     = (const int*)  d_in[3];
    const int*   distances_idx = (const int*)  d_in[4];
    const float* Win           = (const float*)d_in[5];
    const float* b_in          = (const float*)d_in[6];
    const float* z             = (const float*)d_in[7];
    const float* b_spatial     = (const float*)d_in[8];
    const float* Wq            = (const float*)d_in[9];
    const float* bq            = (const float*)d_in[10];
    const float* Wk            = (const float*)d_in[11];
    const float* bk            = (const float*)d_in[12];
    const float* Wv            = (const float*)d_in[13];
    const float* bv            = (const float*)d_in[14];
    const float* Wo            = (const float*)d_in[15];
    const float* bo            = (const float*)d_in[16];
    const float* ln1w          = (const float*)d_in[17];
    const float* ln1b          = (const float*)d_in[18];
    const float* ln2w          = (const float*)d_in[19];
    const float* ln2b          = (const float*)d_in[20];
    const float* Wff           = (const float*)d_in[21];
    const float* bff           = (const float*)d_in[22];
    const float* Wout          = (const float*)d_in[23];
    const float* bout          = (const float*)d_in[24];
    float* out = (float*)d_out;

    float *p_h, *p_hn, *p_xp, *p_q, *p_k, *p_v, *p_o, *p_S, *p_bmat, *p_rmax, *p_rinv;
    cudaGetSymbolAddress((void**)&p_h,  g_h);
    cudaGetSymbolAddress((void**)&p_hn, g_hn);
    cudaGetSymbolAddress((void**)&p_xp, g_xp);
    cudaGetSymbolAddress((void**)&p_q,  g_q);
    cudaGetSymbolAddress((void**)&p_k,  g_k);
    cudaGetSymbolAddress((void**)&p_v,  g_v);
    cudaGetSymbolAddress((void**)&p_o,  g_o);
    cudaGetSymbolAddress((void**)&p_S,  g_S);
    cudaGetSymbolAddress((void**)&p_bmat, g_bmat);
    cudaGetSymbolAddress((void**)&p_rmax, g_rmax);
    cudaGetSymbolAddress((void**)&p_rinv, g_rinv);
    __nv_bfloat16 *p_khi, *p_klo, *p_vthi, *p_vtlo;
    __nv_bfloat16 *p_wqhi, *p_wqlo, *p_wkhi, *p_wklo, *p_wvhi, *p_wvlo;
    __nv_bfloat16 *p_wohi, *p_wolo, *p_wffhi, *p_wfflo;
    cudaGetSymbolAddress((void**)&p_khi,  g_khi);
    cudaGetSymbolAddress((void**)&p_klo,  g_klo);
    cudaGetSymbolAddress((void**)&p_vthi, g_vthi);
    cudaGetSymbolAddress((void**)&p_vtlo, g_vtlo);
    cudaGetSymbolAddress((void**)&p_wqhi, g_wqhi);
    cudaGetSymbolAddress((void**)&p_wqlo, g_wqlo);
    cudaGetSymbolAddress((void**)&p_wkhi, g_wkhi);
    cudaGetSymbolAddress((void**)&p_wklo, g_wklo);
    cudaGetSymbolAddress((void**)&p_wvhi, g_wvhi);
    cudaGetSymbolAddress((void**)&p_wvlo, g_wvlo);
    cudaGetSymbolAddress((void**)&p_wohi, g_wohi);
    cudaGetSymbolAddress((void**)&p_wolo, g_wolo);
    cudaGetSymbolAddress((void**)&p_wffhi, g_wffhi);
    cudaGetSymbolAddress((void**)&p_wfflo, g_wfflo);

    cudaFuncSetAttribute(tcgemm<0,0>, cudaFuncAttributeMaxDynamicSharedMemorySize, TCG_SMEM);
    cudaFuncSetAttribute(tcgemm<0,1>, cudaFuncAttributeMaxDynamicSharedMemorySize, TCG_SMEM);
    cudaFuncSetAttribute(tcgemm<1,0>, cudaFuncAttributeMaxDynamicSharedMemorySize, TCG_SMEM);

    // ---- preamble ----
    zero_deg_kernel<<<(NODES+255)/256, 256>>>();
    zero_bmat_kernel<<<2048, 256>>>();
    deg_kernel<<<EDGES/256, 256>>>(edge_index);
    input_kernel<<<NODES, 256>>>(x, Win, b_in, z);
    scatter_kernel<<<(PAIRS+255)/256, 256>>>(distances_idx, distances, b_spatial);

    // ---- weight prep (transpose + bf16 split) ----
    tsplit_kernel<<<dim3(8, 8, LAYERS*HEADS), dim3(32,8)>>>(Wq, DIM*DIM, DIM, DIM, p_wqhi, p_wqlo, DIM*DIM);
    tsplit_kernel<<<dim3(8, 8, LAYERS*HEADS), dim3(32,8)>>>(Wk, DIM*DIM, DIM, DIM, p_wkhi, p_wklo, DIM*DIM);
    tsplit_kernel<<<dim3(8, 8, LAYERS*HEADS), dim3(32,8)>>>(Wv, DIM*DIM, DIM, DIM, p_wvhi, p_wvlo, DIM*DIM);
    tsplit_kernel<<<dim3(8, 64, LAYERS), dim3(32,8)>>>(Wo, (long long)HEADS*DIM*DIM, HEADS*DIM, DIM,
                                                       p_wohi, p_wolo, (long long)HEADS*DIM*DIM);
    tsplit_kernel<<<dim3(8, 8, LAYERS), dim3(32,8)>>>(Wff, DIM*DIM, DIM, DIM, p_wffhi, p_wfflo, DIM*DIM);

    const long long ND  = (long long)NODES*DIM;
    const long long NN2 = (long long)NODES*NODES;
    const int splitN4 = HEADS*NODES*DIM/4;

    for (int l = 0; l < LAYERS; l++) {
        ln_kernel<<<NODES, 256>>>(p_h, p_hn, ln1w + l*DIM, ln1b + l*DIM);

        // Q/K/V projections (batched over heads)
        dim3 gq(DIM/128, NODES/128, HEADS);
        tcgemm<0,0><<<gq, 256, TCG_SMEM>>>(p_hn, 0, DIM,
                p_wqhi + (size_t)l*HEADS*DIM*DIM, p_wqlo + (size_t)l*HEADS*DIM*DIM, DIM*DIM, DIM,
                p_q, ND, DIM, DIM, bq + (size_t)l*HEADS*DIM, DIM, nullptr, 0,
                nullptr, nullptr, nullptr, nullptr);
        tcgemm<0,0><<<gq, 256, TCG_SMEM>>>(p_hn, 0, DIM,
                p_wkhi + (size_t)l*HEADS*DIM*DIM, p_wklo + (size_t)l*HEADS*DIM*DIM, DIM*DIM, DIM,
                p_k, ND, DIM, DIM, bk + (size_t)l*HEADS*DIM, DIM, nullptr, 0,
                nullptr, nullptr, nullptr, nullptr);
        tcgemm<0,0><<<gq, 256, TCG_SMEM>>>(p_hn, 0, DIM,
                p_wvhi + (size_t)l*HEADS*DIM*DIM, p_wvlo + (size_t)l*HEADS*DIM*DIM, DIM*DIM, DIM,
                p_v, ND, DIM, DIM, bv + (size_t)l*HEADS*DIM, DIM, nullptr, 0,
                nullptr, nullptr, nullptr, nullptr);

        // split K, transpose+split V
        split_kernel<<<(splitN4+255)/256, 256>>>(p_k, p_khi, p_klo, splitN4);
        tsplit_kernel<<<dim3(8, 64, HEADS), dim3(32,8)>>>(p_v, ND, NODES, DIM, p_vthi, p_vtlo, ND);

        // S' = (Q K^T * scale + bmat) * mneg   (fused epilogue, per head)
        dim3 gs(NODES/128, NODES/128, HEADS);
        tcgemm<0,1><<<gs, 256, TCG_SMEM>>>(p_q, ND, DIM, p_khi, p_klo, ND, DIM,
                p_S, NN2, NODES, DIM, nullptr, 0, nullptr, 0,
                ptr, nullptr, nullptr, p_bmat);

        // per-row max / denom (dead-row detection)
        rowstat_kernel<<<dim3(NODES, HEADS), 256>>>(ptr);

        // O = softmax(S') * mzero @ V   (prob computed in loader; dead tiles skipped)
        dim3 go(DIM/128, NODES/128, HEADS);
        tcgemm<1,0><<<go, 256, TCG_SMEM>>>(p_S, NN2, NODES, p_vthi, p_vtlo, ND, NODES,
                p_o, DIM, HEADS*DIM, NODES, nullptr, 0, nullptr, 0,
                ptr, p_rmax, p_rinv, nullptr);

        // xp = o Wo + bo + h
        dim3 gw(DIM/128, NODES/128, 1);
        tcgemm<0,0><<<gw, 256, TCG_SMEM>>>(p_o, 0, HEADS*DIM,
                p_wohi + (size_t)l*HEADS*DIM*DIM, p_wolo + (size_t)l*HEADS*DIM*DIM, 0, HEADS*DIM,
                p_xp, 0, DIM, HEADS*DIM, bo + (size_t)l*DIM, 0, p_h, DIM,
                nullptr, nullptr, nullptr, nullptr);

        ln_kernel<<<NODES, 256>>>(p_xp, p_hn, ln2w + l*DIM, ln2b + l*DIM);

        // h = LN2(xp) Wff + bff + xp
        tcgemm<0,0><<<gw, 256, TCG_SMEM>>>(p_hn, 0, DIM,
                p_wffhi + (size_t)l*DIM*DIM, p_wfflo + (size_t)l*DIM*DIM, 0, DIM,
                p_h, 0, DIM, DIM, bff + (size_t)l*DIM, 0, p_xp, DIM,
                nullptr, nullptr, nullptr, nullptr);
    }

    out_kernel<<<NODES, DOUTV>>>(Wout, bout, out);
}

// round 9
// speedup vs baseline: 1.0015x; 1.0015x over previous
#include <cuda_runtime.h>
#include <cuda_bf16.h>
#include <cstdint>
#include <cstddef>

// ---------------- problem constants ----------------
#define NODES 2048
#define EDGES 65536
#define PAIRS 1000000
#define LAYERS 4
#define HEADS 8
#define DIM 256
#define DINV 128
#define DOUTV 64
#define MAXDEGV 64
#define MPDV 10
#define SCALEQ 0.0625f

// ---------------- device scratch (no allocation allowed) ----------------
__device__ __align__(16) float g_h [NODES*DIM];
__device__ __align__(16) float g_hn[NODES*DIM];
__device__ __align__(16) float g_xp[NODES*DIM];
__device__ __align__(16) float g_q [HEADS*NODES*DIM];
__device__ __align__(16) float g_k [HEADS*NODES*DIM];
__device__ __align__(16) float g_v [HEADS*NODES*DIM];
__device__ __align__(16) float g_o [NODES*HEADS*DIM];
__device__ __align__(16) float g_S [(size_t)HEADS*NODES*NODES];
__device__ __align__(16) float g_bmat[(size_t)NODES*NODES];
__device__ int   g_deg[NODES];
__device__ float g_rmax[HEADS*NODES];
__device__ float g_rinv[HEADS*NODES];

// bf16 split operands
__device__ __align__(16) __nv_bfloat16 g_khi [HEADS*NODES*DIM];
__device__ __align__(16) __nv_bfloat16 g_klo [HEADS*NODES*DIM];
__device__ __align__(16) __nv_bfloat16 g_vthi[HEADS*NODES*DIM];
__device__ __align__(16) __nv_bfloat16 g_vtlo[HEADS*NODES*DIM];
__device__ __align__(16) __nv_bfloat16 g_wqhi[LAYERS*HEADS*DIM*DIM];
__device__ __align__(16) __nv_bfloat16 g_wqlo[LAYERS*HEADS*DIM*DIM];
__device__ __align__(16) __nv_bfloat16 g_wkhi[LAYERS*HEADS*DIM*DIM];
__device__ __align__(16) __nv_bfloat16 g_wklo[LAYERS*HEADS*DIM*DIM];
__device__ __align__(16) __nv_bfloat16 g_wvhi[LAYERS*HEADS*DIM*DIM];
__device__ __align__(16) __nv_bfloat16 g_wvlo[LAYERS*HEADS*DIM*DIM];
__device__ __align__(16) __nv_bfloat16 g_wohi[LAYERS*HEADS*DIM*DIM];
__device__ __align__(16) __nv_bfloat16 g_wolo[LAYERS*HEADS*DIM*DIM];
__device__ __align__(16) __nv_bfloat16 g_wffhi[LAYERS*DIM*DIM];
__device__ __align__(16) __nv_bfloat16 g_wfflo[LAYERS*DIM*DIM];

// ---------------- helpers ----------------
__device__ __forceinline__ uint32_t smem_to_u32(const void* p) {
    uint32_t a;
    asm("{ .reg .u64 t; cvta.to.shared.u64 t, %1; cvt.u32.u64 %0, t; }" : "=r"(a) : "l"(p));
    return a;
}
__device__ __forceinline__ uint32_t pack_bf2(__nv_bfloat16 a, __nv_bfloat16 b) {
    return (uint32_t)__bfloat16_as_ushort(a) | ((uint32_t)__bfloat16_as_ushort(b) << 16);
}
__device__ __forceinline__ void ldsm4(uint32_t* r, uint32_t addr) {
    asm volatile("ldmatrix.sync.aligned.m8n8.x4.shared.b16 {%0,%1,%2,%3}, [%4];"
        : "=r"(r[0]), "=r"(r[1]), "=r"(r[2]), "=r"(r[3]) : "r"(addr));
}
__device__ __forceinline__ void ldsm2(uint32_t* r, uint32_t addr) {
    asm volatile("ldmatrix.sync.aligned.m8n8.x2.shared.b16 {%0,%1}, [%2];"
        : "=r"(r[0]), "=r"(r[1]) : "r"(addr));
}
__device__ __forceinline__ void mma_bf16(float* d, const uint32_t* a, const uint32_t* b) {
    asm volatile("mma.sync.aligned.m16n8k16.row.col.f32.bf16.bf16.f32 "
        "{%0,%1,%2,%3}, {%4,%5,%6,%7}, {%8,%9}, {%0,%1,%2,%3};"
        : "+f"(d[0]), "+f"(d[1]), "+f"(d[2]), "+f"(d[3])
        : "r"(a[0]), "r"(a[1]), "r"(a[2]), "r"(a[3]), "r"(b[0]), "r"(b[1]));
}

// ---------------- utility kernels ----------------
__global__ void zero_deg_kernel() {
    int i = blockIdx.x * blockDim.x + threadIdx.x;
    if (i < NODES) g_deg[i] = 0;
}
__global__ void zero_bmat_kernel() {
    size_t i = (size_t)blockIdx.x * blockDim.x + threadIdx.x;
    size_t stride = (size_t)gridDim.x * blockDim.x;
    for (; i < (size_t)NODES*NODES; i += stride) g_bmat[i] = 0.f;
}
__global__ void deg_kernel(const int* __restrict__ edge_index) {
    int e = blockIdx.x * blockDim.x + threadIdx.x;
    if (e < EDGES) atomicAdd(&g_deg[edge_index[e]], 1);
}
__global__ void scatter_kernel(const int* __restrict__ dindex,
                               const int* __restrict__ dist,
                               const float* __restrict__ bsp) {
    int p = blockIdx.x * blockDim.x + threadIdx.x;
    if (p >= PAIRS) return;
    int i = dindex[p];
    int j = dindex[PAIRS + p];
    int d = dist[p];
    d = d < 0 ? 0 : (d > MPDV-1 ? MPDV-1 : d);
    g_bmat[(size_t)i*NODES + j] = bsp[d];
}

__global__ void input_kernel(const float* __restrict__ x,
                             const float* __restrict__ Win,
                             const float* __restrict__ b_in,
                             const float* __restrict__ z) {
    int row = blockIdx.x;
    int c   = threadIdx.x;
    __shared__ float xs[DINV];
    if (c < DINV) xs[c] = x[row*DINV + c];
    __syncthreads();
    float acc = 0.f;
    #pragma unroll 8
    for (int k = 0; k < DINV; k++) acc += xs[k] * Win[k*DIM + c];
    int d = g_deg[row];
    if (d > MAXDEGV-1) d = MAXDEGV-1;
    g_h[row*DIM + c] = acc + b_in[c] + z[d*DIM + c];
}

__global__ void ln_kernel(const float* __restrict__ x, float* __restrict__ y,
                          const float* __restrict__ w, const float* __restrict__ b) {
    int row = blockIdx.x;
    int t = threadIdx.x;
    __shared__ float red[256];
    float v = x[row*DIM + t];
    red[t] = v; __syncthreads();
    #pragma unroll
    for (int s = 128; s > 0; s >>= 1) { if (t < s) red[t] += red[t+s]; __syncthreads(); }
    float mu = red[0] * (1.f/DIM);
    __syncthreads();
    float d = v - mu;
    red[t] = d*d; __syncthreads();
    #pragma unroll
    for (int s = 128; s > 0; s >>= 1) { if (t < s) red[t] += red[t+s]; __syncthreads(); }
    float var = red[0] * (1.f/DIM);
    y[row*DIM + t] = d * rsqrtf(var + 1e-5f) * w[t] + b[t];
}

// row stats over masked scores s' (already scaled + biased + mneg-multiplied).
// dead row (all same-graph exps underflow): rinv = 0.
__global__ void __launch_bounds__(256) rowstat_kernel(const int* __restrict__ gptr) {
    int row = blockIdx.x, h = blockIdx.y;
    const float* srow = g_S + ((size_t)h*NODES + row)*NODES;
    __shared__ float sv[NODES];
    __shared__ int   sp[NODES];
    __shared__ float red[256];
    int t = threadIdx.x;
    for (int j = t; j < NODES; j += 256) { sv[j] = srow[j]; sp[j] = gptr[j]; }
    __syncthreads();
    int pn = sp[row];
    float mall = -3.4e38f, msame = -3.4e38f;
    for (int j = t; j < NODES; j += 256) {
        float xv = sv[j];
        mall = fmaxf(mall, xv);
        if (sp[j] == pn) msame = fmaxf(msame, xv);
    }
    red[t] = mall; __syncthreads();
    #pragma unroll
    for (int s = 128; s > 0; s >>= 1) { if (t < s) red[t] = fmaxf(red[t], red[t+s]); __syncthreads(); }
    mall = red[0]; __syncthreads();
    red[t] = msame; __syncthreads();
    #pragma unroll
    for (int s = 128; s > 0; s >>= 1) { if (t < s) red[t] = fmaxf(red[t], red[t+s]); __syncthreads(); }
    msame = red[0]; __syncthreads();

    float rmax, rinv;
    if (mall - msame > 80.f) {
        rmax = 3.4e38f; rinv = 0.f;      // dead row: attention output exactly ~0
    } else {
        float s = 0.f;                    // rare path: exact reference denominator
        for (int j = t; j < NODES; j += 256) s += __expf(sv[j] - mall);
        red[t] = s; __syncthreads();
        #pragma unroll
        for (int q = 128; q > 0; q >>= 1) { if (t < q) red[t] += red[t+q]; __syncthreads(); }
        rmax = mall; rinv = 1.f / red[0];
    }
    if (t == 0) { g_rmax[h*NODES + row] = rmax; g_rinv[h*NODES + row] = rinv; }
}

// elementwise fp32 -> bf16 hi/lo split (same layout)
__global__ void split_kernel(const float* __restrict__ in,
                             __nv_bfloat16* __restrict__ hi,
                             __nv_bfloat16* __restrict__ lo, int n4) {
    int i = blockIdx.x * blockDim.x + threadIdx.x;
    if (i >= n4) return;
    float4 v = ((const float4*)in)[i];
    __nv_bfloat16 h0 = __float2bfloat16(v.x);
    __nv_bfloat16 h1 = __float2bfloat16(v.y);
    __nv_bfloat16 h2 = __float2bfloat16(v.z);
    __nv_bfloat16 h3 = __float2bfloat16(v.w);
    __nv_bfloat16 l0 = __float2bfloat16(v.x - __bfloat162float(h0));
    __nv_bfloat16 l1 = __float2bfloat16(v.y - __bfloat162float(h1));
    __nv_bfloat16 l2 = __float2bfloat16(v.z - __bfloat162float(h2));
    __nv_bfloat16 l3 = __float2bfloat16(v.w - __bfloat162float(h3));
    ((uint2*)hi)[i] = make_uint2(pack_bf2(h0,h1), pack_bf2(h2,h3));
    ((uint2*)lo)[i] = make_uint2(pack_bf2(l0,l1), pack_bf2(l2,l3));
}

// transpose + split: in [batch][Krows][Ncols] fp32 -> out [batch][Ncols][Krows] bf16 hi/lo
__global__ void tsplit_kernel(const float* __restrict__ in, long long inB,
                              int Krows, int Ncols,
                              __nv_bfloat16* __restrict__ hi,
                              __nv_bfloat16* __restrict__ lo, long long outB) {
    __shared__ float t[32][33];
    const float* inb = in + (size_t)blockIdx.z * inB;
    int n0 = blockIdx.x * 32, k0 = blockIdx.y * 32;
    #pragma unroll
    for (int j = 0; j < 4; j++)
        t[threadIdx.y + j*8][threadIdx.x] =
            inb[(size_t)(k0 + threadIdx.y + j*8) * Ncols + n0 + threadIdx.x];
    __syncthreads();
    size_t ob = (size_t)blockIdx.z * outB;
    #pragma unroll
    for (int j = 0; j < 4; j++) {
        int n = threadIdx.y + j*8;
        float v = t[threadIdx.x][n];
        size_t o = ob + (size_t)(n0 + n) * Krows + k0 + threadIdx.x;
        __nv_bfloat16 hv = __float2bfloat16(v);
        hi[o] = hv;
        lo[o] = __float2bfloat16(v - __bfloat162float(hv));
    }
}

// ---------------- split-bf16 GEMM via mma.sync ----------
// AMODE 0: A fp32 plain.  AMODE 1: A = masked scores s'; loader computes
//          p = exp(s'-rmax)*rinv for same-graph cols, 0 otherwise; per-CTA
//          early-out (zero tile) when all 128 rows dead.
// EPI 0: optional bias[n] + residual add.  EPI 1: attention score epilogue:
//          s' = (acc*SCALEQ + bmat[m][n]) * (ptr[m]==ptr[n] ? 1 : -1e6).
#define KC 64
#define PADE 72
#define SA_HI 0
#define SA_LO 18432
#define SB_HI 36864
#define SB_LO 55296
#define TCG_SMEM 73728

template<int AMODE, int EPI>
__global__ void __launch_bounds__(256, 1) tcgemm(
        const float* __restrict__ A, long long aB, int lda,
        const __nv_bfloat16* __restrict__ Bhi, const __nv_bfloat16* __restrict__ Blo,
        long long bB, int ldb,
        float* __restrict__ C, long long cB, int ldc, int K,
        const float* __restrict__ bias, long long biasB,
        const float* __restrict__ res, int ldres,
        const int* __restrict__ gptr, const float* __restrict__ rmax,
        const float* __restrict__ rinv, const float* __restrict__ bmatp) {
    extern __shared__ char smc[];
    uint32_t sbase = smem_to_u32(smc);

    int tid = threadIdx.x;
    int wid = tid >> 5, lane = tid & 31;
    int m0 = blockIdx.y * 128, n0 = blockIdx.x * 128;
    const float* Ab = A + (size_t)blockIdx.z * aB + (size_t)m0 * lda;
    const __nv_bfloat16* Bh = Bhi + (size_t)blockIdx.z * bB + (size_t)n0 * ldb;
    const __nv_bfloat16* Bl = Blo + (size_t)blockIdx.z * bB + (size_t)n0 * ldb;
    float* Cb = C + (size_t)blockIdx.z * cB;

    // loader indices
    int ra = tid >> 4, ca = (tid & 15) * 4;   // A: float4
    int rb = tid >> 3, cb = (tid & 7) * 8;    // B: uint4 (8 bf16)

    float prm[8], pri[8];
    int   ppm[8];
    if (AMODE == 1) {
        __shared__ int s_alive;
        if (tid == 0) s_alive = 0;
        __syncthreads();
        if (tid < 128 && rinv[(size_t)blockIdx.z*NODES + m0 + tid] != 0.f) s_alive = 1;
        __syncthreads();
        if (!s_alive) {       // all rows dead -> output tile is exactly zero
            float4 z4 = make_float4(0.f, 0.f, 0.f, 0.f);
            for (int idx = tid; idx < 128*32; idx += 256) {
                int r = idx >> 5, c4 = idx & 31;
                *(float4*)(Cb + (size_t)(m0 + r)*ldc + n0 + c4*4) = z4;
            }
            return;
        }
        #pragma unroll
        for (int p = 0; p < 8; p++) {
            int gr = m0 + p*16 + ra;
            prm[p] = rmax[(size_t)blockIdx.z*NODES + gr];
            pri[p] = rinv[(size_t)blockIdx.z*NODES + gr];
            ppm[p] = gptr[gr];
        }
    }

    // warp tile origin
    int wm = (wid & 1) * 64;
    int wn = (wid >> 1) * 32;

    uint32_t aAddr = sbase + ((uint32_t)((wm + (lane & 15)) * PADE + ((lane >> 4) << 3)) << 1);
    int l2 = lane & 15;
    uint32_t bAddr = sbase + ((uint32_t)((wn + (l2 & 7)) * PADE + (((l2 >> 3) & 1) << 3)) << 1);

    float acc[4][4][4];
    #pragma unroll
    for (int i = 0; i < 4; i++)
        #pragma unroll
        for (int j = 0; j < 4; j++)
            #pragma unroll
            for (int q = 0; q < 4; q++) acc[i][j][q] = 0.f;

    // prefetch chunk 0
    float4 pa[8];
    uint4 pbh[4], pbl[4];
    int4 pcv = make_int4(0,0,0,0);
    #pragma unroll
    for (int p = 0; p < 8; p++)
        pa[p] = *(const float4*)(Ab + (size_t)(p*16 + ra)*lda + ca);
    if (AMODE == 1) pcv = *(const int4*)(gptr + ca);
    #pragma unroll
    for (int p = 0; p < 4; p++) {
        pbh[p] = *(const uint4*)(Bh + (size_t)(p*32 + rb)*ldb + cb);
        pbl[p] = *(const uint4*)(Bl + (size_t)(p*32 + rb)*ldb + cb);
    }

    int nch = K / KC;
    for (int c = 0; c < nch; c++) {
        __syncthreads();
        #pragma unroll
        for (int p = 0; p < 8; p++) {
            float4 v = pa[p];
            if (AMODE == 1) {
                float4 q;
                if (pri[p] == 0.f) {
                    q = make_float4(0.f, 0.f, 0.f, 0.f);
                } else {
                    bool b0 = (pcv.x == ppm[p]), b1 = (pcv.y == ppm[p]);
                    bool b2 = (pcv.z == ppm[p]), b3 = (pcv.w == ppm[p]);
                    if (b0 | b1 | b2 | b3) {
                        float rm = prm[p], ri = pri[p];
                        q.x = b0 ? __expf(v.x - rm) * ri : 0.f;
                        q.y = b1 ? __expf(v.y - rm) * ri : 0.f;
                        q.z = b2 ? __expf(v.z - rm) * ri : 0.f;
                        q.w = b3 ? __expf(v.w - rm) * ri : 0.f;
                    } else {
                        q = make_float4(0.f, 0.f, 0.f, 0.f);
                    }
                }
                v = q;
            }
            __nv_bfloat16 h0 = __float2bfloat16(v.x);
            __nv_bfloat16 h1 = __float2bfloat16(v.y);
            __nv_bfloat16 h2 = __float2bfloat16(v.z);
            __nv_bfloat16 h3 = __float2bfloat16(v.w);
            __nv_bfloat16 l0 = __float2bfloat16(v.x - __bfloat162float(h0));
            __nv_bfloat16 l1 = __float2bfloat16(v.y - __bfloat162float(h1));
            __nv_bfloat16 l2b = __float2bfloat16(v.z - __bfloat162float(h2));
            __nv_bfloat16 l3 = __float2bfloat16(v.w - __bfloat162float(h3));
            uint32_t off = (uint32_t)(((p*16 + ra)*PADE + ca) << 1);
            *(uint2*)(smc + SA_HI + off) = make_uint2(pack_bf2(h0,h1), pack_bf2(h2,h3));
            *(uint2*)(smc + SA_LO + off) = make_uint2(pack_bf2(l0,l1), pack_bf2(l2b,l3));
        }
        #pragma unroll
        for (int p = 0; p < 4; p++) {
            uint32_t off = (uint32_t)(((p*32 + rb)*PADE + cb) << 1);
            *(uint4*)(smc + SB_HI + off) = pbh[p];
            *(uint4*)(smc + SB_LO + off) = pbl[p];
        }
        if (c + 1 < nch) {
            int k0 = (c + 1) * KC;
            #pragma unroll
            for (int p = 0; p < 8; p++)
                pa[p] = *(const float4*)(Ab + (size_t)(p*16 + ra)*lda + k0 + ca);
            if (AMODE == 1) pcv = *(const int4*)(gptr + k0 + ca);
            #pragma unroll
            for (int p = 0; p < 4; p++) {
                pbh[p] = *(const uint4*)(Bh + (size_t)(p*32 + rb)*ldb + k0 + cb);
                pbl[p] = *(const uint4*)(Bl + (size_t)(p*32 + rb)*ldb + k0 + cb);
            }
        }
        __syncthreads();
        #pragma unroll
        for (int kk = 0; kk < 4; kk++) {
            uint32_t ah[4][4], al[4][4], bh2[4][2], bl2[4][2];
            #pragma unroll
            for (int i = 0; i < 4; i++) {
                uint32_t ao = (uint32_t)(i*16*PADE*2 + kk*32);
                ldsm4(ah[i], aAddr + SA_HI + ao);
                ldsm4(al[i], aAddr + SA_LO + ao);
            }
            #pragma unroll
            for (int j = 0; j < 4; j++) {
                uint32_t bo = (uint32_t)(j*8*PADE*2 + kk*32);
                ldsm2(bh2[j], bAddr + SB_HI + bo);
                ldsm2(bl2[j], bAddr + SB_LO + bo);
            }
            #pragma unroll
            for (int i = 0; i < 4; i++)
                #pragma unroll
                for (int j = 0; j < 4; j++) {
                    mma_bf16(acc[i][j], ah[i], bh2[j]);
                    mma_bf16(acc[i][j], ah[i], bl2[j]);
                    mma_bf16(acc[i][j], al[i], bh2[j]);
                }
        }
    }

    int g = lane >> 2, t = lane & 3;
    if (EPI == 1) {
        // attention score epilogue: s' = (acc*scale + bmat) * mneg
        #pragma unroll
        for (int i = 0; i < 4; i++) {
            int m = m0 + wm + i*16 + g;
            int pma = gptr[m], pmb = gptr[m+8];
            const float* bra = bmatp + (size_t)m*NODES;
            const float* brb = bmatp + (size_t)(m+8)*NODES;
            #pragma unroll
            for (int j = 0; j < 4; j++) {
                int n = n0 + wn + j*8 + t*2;
                int pn0 = gptr[n], pn1 = gptr[n+1];
                float2 b0 = *(const float2*)(bra + n);
                float2 b1 = *(const float2*)(brb + n);
                float s00 = acc[i][j][0]*SCALEQ + b0.x;
                float s01 = acc[i][j][1]*SCALEQ + b0.y;
                float s10 = acc[i][j][2]*SCALEQ + b1.x;
                float s11 = acc[i][j][3]*SCALEQ + b1.y;
                s00 = (pma == pn0) ? s00 : s00 * -1e6f;
                s01 = (pma == pn1) ? s01 : s01 * -1e6f;
                s10 = (pmb == pn0) ? s10 : s10 * -1e6f;
                s11 = (pmb == pn1) ? s11 : s11 * -1e6f;
                *(float2*)(Cb + (size_t)m*ldc + n)     = make_float2(s00, s01);
                *(float2*)(Cb + (size_t)(m+8)*ldc + n) = make_float2(s10, s11);
            }
        }
    } else {
        const float* biasb = bias ? bias + (size_t)blockIdx.z * biasB : nullptr;
        #pragma unroll
        for (int i = 0; i < 4; i++) {
            int m = m0 + wm + i*16 + g;
            #pragma unroll
            for (int j = 0; j < 4; j++) {
                int n = n0 + wn + j*8 + t*2;
                float2 v0 = make_float2(acc[i][j][0], acc[i][j][1]);
                float2 v1 = make_float2(acc[i][j][2], acc[i][j][3]);
                if (biasb) {
                    float b0 = biasb[n], b1 = biasb[n+1];
                    v0.x += b0; v0.y += b1;
                    v1.x += b0; v1.y += b1;
                }
                if (res) {
                    float2 r0 = *(const float2*)(res + (size_t)m*ldres + n);
                    float2 r1 = *(const float2*)(res + (size_t)(m+8)*ldres + n);
                    v0.x += r0.x; v0.y += r0.y;
                    v1.x += r1.x; v1.y += r1.y;
                }
                *(float2*)(Cb + (size_t)m*ldc + n)     = v0;
                *(float2*)(Cb + (size_t)(m+8)*ldc + n) = v1;
            }
        }
    }
}

// out = h @ Wout + b_out
__global__ void out_kernel(const float* __restrict__ Wout,
                           const float* __restrict__ bout,
                           float* __restrict__ out) {
    int row = blockIdx.x;
    int c = threadIdx.x;
    __shared__ float hs[DIM];
    for (int k = c; k < DIM; k += DOUTV) hs[k] = g_h[row*DIM + k];
    __syncthreads();
    float acc = 0.f;
    #pragma unroll 8
    for (int k = 0; k < DIM; k++) acc += hs[k] * Wout[k*DOUTV + c];
    out[row*DOUTV + c] = acc + bout[c];
}

// ---------------- launch ----------------
extern "C" void kernel_launch(void* const* d_in, const int* in_sizes, int n_in,
                              void* d_out, int out_size) {
    (void)in_sizes; (void)n_in; (void)out_size;
    const float* x             = (const float*)d_in[0];
    const int*   edge_index    = (const int*)  d_in[1];
    const int*   ptr           = (const int*)  d_in[2];
    const int*   distances     = (const int*)  d_in[3];
    const int*   distances_idx = (const int*)  d_in[4];
    const float* Win           = (const float*)d_in[5];
    const float* b_in          = (const float*)d_in[6];
    const float* z             = (const float*)d_in[7];
    const float* b_spatial     = (const float*)d_in[8];
    const float* Wq            = (const float*)d_in[9];
    const float* bq            = (const float*)d_in[10];
    const float* Wk            = (const float*)d_in[11];
    const float* bk            = (const float*)d_in[12];
    const float* Wv            = (const float*)d_in[13];
    const float* bv            = (const float*)d_in[14];
    const float* Wo            = (const float*)d_in[15];
    const float* bo            = (const float*)d_in[16];
    const float* ln1w          = (const float*)d_in[17];
    const float* ln1b          = (const float*)d_in[18];
    const float* ln2w          = (const float*)d_in[19];
    const float* ln2b          = (const float*)d_in[20];
    const float* Wff           = (const float*)d_in[21];
    const float* bff           = (const float*)d_in[22];
    const float* Wout          = (const float*)d_in[23];
    const float* bout          = (const float*)d_in[24];
    float* out = (float*)d_out;

    float *p_h, *p_hn, *p_xp, *p_q, *p_k, *p_v, *p_o, *p_S, *p_bmat, *p_rmax, *p_rinv;
    cudaGetSymbolAddress((void**)&p_h,  g_h);
    cudaGetSymbolAddress((void**)&p_hn, g_hn);
    cudaGetSymbolAddress((void**)&p_xp, g_xp);
    cudaGetSymbolAddress((void**)&p_q,  g_q);
    cudaGetSymbolAddress((void**)&p_k,  g_k);
    cudaGetSymbolAddress((void**)&p_v,  g_v);
    cudaGetSymbolAddress((void**)&p_o,  g_o);
    cudaGetSymbolAddress((void**)&p_S,  g_S);
    cudaGetSymbolAddress((void**)&p_bmat, g_bmat);
    cudaGetSymbolAddress((void**)&p_rmax, g_rmax);
    cudaGetSymbolAddress((void**)&p_rinv, g_rinv);
    __nv_bfloat16 *p_khi, *p_klo, *p_vthi, *p_vtlo;
    __nv_bfloat16 *p_wqhi, *p_wqlo, *p_wkhi, *p_wklo, *p_wvhi, *p_wvlo;
    __nv_bfloat16 *p_wohi, *p_wolo, *p_wffhi, *p_wfflo;
    cudaGetSymbolAddress((void**)&p_khi,  g_khi);
    cudaGetSymbolAddress((void**)&p_klo,  g_klo);
    cudaGetSymbolAddress((void**)&p_vthi, g_vthi);
    cudaGetSymbolAddress((void**)&p_vtlo, g_vtlo);
    cudaGetSymbolAddress((void**)&p_wqhi, g_wqhi);
    cudaGetSymbolAddress((void**)&p_wqlo, g_wqlo);
    cudaGetSymbolAddress((void**)&p_wkhi, g_wkhi);
    cudaGetSymbolAddress((void**)&p_wklo, g_wklo);
    cudaGetSymbolAddress((void**)&p_wvhi, g_wvhi);
    cudaGetSymbolAddress((void**)&p_wvlo, g_wvlo);
    cudaGetSymbolAddress((void**)&p_wohi, g_wohi);
    cudaGetSymbolAddress((void**)&p_wolo, g_wolo);
    cudaGetSymbolAddress((void**)&p_wffhi, g_wffhi);
    cudaGetSymbolAddress((void**)&p_wfflo, g_wfflo);

    cudaFuncSetAttribute(tcgemm<0,0>, cudaFuncAttributeMaxDynamicSharedMemorySize, TCG_SMEM);
    cudaFuncSetAttribute(tcgemm<0,1>, cudaFuncAttributeMaxDynamicSharedMemorySize, TCG_SMEM);
    cudaFuncSetAttribute(tcgemm<1,0>, cudaFuncAttributeMaxDynamicSharedMemorySize, TCG_SMEM);

    // ---- preamble ----
    zero_deg_kernel<<<(NODES+255)/256, 256>>>();
    zero_bmat_kernel<<<2048, 256>>>();
    deg_kernel<<<EDGES/256, 256>>>(edge_index);
    input_kernel<<<NODES, 256>>>(x, Win, b_in, z);
    scatter_kernel<<<(PAIRS+255)/256, 256>>>(distances_idx, distances, b_spatial);

    // ---- weight prep (transpose + bf16 split) ----
    tsplit_kernel<<<dim3(8, 8, LAYERS*HEADS), dim3(32,8)>>>(Wq, DIM*DIM, DIM, DIM, p_wqhi, p_wqlo, DIM*DIM);
    tsplit_kernel<<<dim3(8, 8, LAYERS*HEADS), dim3(32,8)>>>(Wk, DIM*DIM, DIM, DIM, p_wkhi, p_wklo, DIM*DIM);
    tsplit_kernel<<<dim3(8, 8, LAYERS*HEADS), dim3(32,8)>>>(Wv, DIM*DIM, DIM, DIM, p_wvhi, p_wvlo, DIM*DIM);
    tsplit_kernel<<<dim3(8, 64, LAYERS), dim3(32,8)>>>(Wo, (long long)HEADS*DIM*DIM, HEADS*DIM, DIM,
                                                       p_wohi, p_wolo, (long long)HEADS*DIM*DIM);
    tsplit_kernel<<<dim3(8, 8, LAYERS), dim3(32,8)>>>(Wff, DIM*DIM, DIM, DIM, p_wffhi, p_wfflo, DIM*DIM);

    const long long ND  = (long long)NODES*DIM;
    const long long NN2 = (long long)NODES*NODES;
    const int splitN4 = HEADS*NODES*DIM/4;

    for (int l = 0; l < LAYERS; l++) {
        ln_kernel<<<NODES, 256>>>(p_h, p_hn, ln1w + l*DIM, ln1b + l*DIM);

        // Q/K/V projections (batched over heads)
        dim3 gq(DIM/128, NODES/128, HEADS);
        tcgemm<0,0><<<gq, 256, TCG_SMEM>>>(p_hn, 0, DIM,
                p_wqhi + (size_t)l*HEADS*DIM*DIM, p_wqlo + (size_t)l*HEADS*DIM*DIM, DIM*DIM, DIM,
                p_q, ND, DIM, DIM, bq + (size_t)l*HEADS*DIM, DIM, nullptr, 0,
                nullptr, nullptr, nullptr, nullptr);
        tcgemm<0,0><<<gq, 256, TCG_SMEM>>>(p_hn, 0, DIM,
                p_wkhi + (size_t)l*HEADS*DIM*DIM, p_wklo + (size_t)l*HEADS*DIM*DIM, DIM*DIM, DIM,
                p_k, ND, DIM, DIM, bk + (size_t)l*HEADS*DIM, DIM, nullptr, 0,
                nullptr, nullptr, nullptr, nullptr);
        tcgemm<0,0><<<gq, 256, TCG_SMEM>>>(p_hn, 0, DIM,
                p_wvhi + (size_t)l*HEADS*DIM*DIM, p_wvlo + (size_t)l*HEADS*DIM*DIM, DIM*DIM, DIM,
                p_v, ND, DIM, DIM, bv + (size_t)l*HEADS*DIM, DIM, nullptr, 0,
                nullptr, nullptr, nullptr, nullptr);

        // split K, transpose+split V
        split_kernel<<<(splitN4+255)/256, 256>>>(p_k, p_khi, p_klo, splitN4);
        tsplit_kernel<<<dim3(8, 64, HEADS), dim3(32,8)>>>(p_v, ND, NODES, DIM, p_vthi, p_vtlo, ND);

        // S' = (Q K^T * scale + bmat) * mneg   (fused epilogue, per head)
        dim3 gs(NODES/128, NODES/128, HEADS);
        tcgemm<0,1><<<gs, 256, TCG_SMEM>>>(p_q, ND, DIM, p_khi, p_klo, ND, DIM,
                p_S, NN2, NODES, DIM, nullptr, 0, nullptr, 0,
                ptr, nullptr, nullptr, p_bmat);

        // per-row max / denom (dead-row detection)
        rowstat_kernel<<<dim3(NODES, HEADS), 256>>>(ptr);

        // O = softmax(S') * mzero @ V   (prob computed in loader; dead tiles skipped)
        dim3 go(DIM/128, NODES/128, HEADS);
        tcgemm<1,0><<<go, 256, TCG_SMEM>>>(p_S, NN2, NODES, p_vthi, p_vtlo, ND, NODES,
                p_o, DIM, HEADS*DIM, NODES, nullptr, 0, nullptr, 0,
                ptr, p_rmax, p_rinv, nullptr);

        // xp = o Wo + bo + h
        dim3 gw(DIM/128, NODES/128, 1);
        tcgemm<0,0><<<gw, 256, TCG_SMEM>>>(p_o, 0, HEADS*DIM,
                p_wohi + (size_t)l*HEADS*DIM*DIM, p_wolo + (size_t)l*HEADS*DIM*DIM, 0, HEADS*DIM,
                p_xp, 0, DIM, HEADS*DIM, bo + (size_t)l*DIM, 0, p_h, DIM,
                nullptr, nullptr, nullptr, nullptr);

        ln_kernel<<<NODES, 256>>>(p_xp, p_hn, ln2w + l*DIM, ln2b + l*DIM);

        // h = LN2(xp) Wff + bff + xp
        tcgemm<0,0><<<gw, 256, TCG_SMEM>>>(p_hn, 0, DIM,
                p_wffhi + (size_t)l*DIM*DIM, p_wfflo + (size_t)l*DIM*DIM, 0, DIM,
                p_h, 0, DIM, DIM, bff + (size_t)l*DIM, 0, p_xp, DIM,
                nullptr, nullptr, nullptr, nullptr);
    }

    out_kernel<<<NODES, DOUTV>>>(Wout, bout, out);
}